// round 8
// baseline (speedup 1.0000x reference)
#include <cuda_runtime.h>
#include <cstdint>
#include <cstddef>

#define B_    2
#define C_    256
#define H_    512
#define W_    512
#define PS    52
#define NH    9
#define NW    9
#define P_    81
#define QQ    2704         // PS*PS
#define PLANE (H_*W_)      // 262144

#define SB_STRIDE 265      // smem row stride (52 rows x 265) -> 55.1 KB dynamic

// Scratch (device globals: no allocations allowed)
__device__ float d_gsum[B_*C_];
__device__ float d_S16[B_*P_*16*256];   // per (b,pp,cg) partial weighted sums
__device__ float d_Q16[B_*P_*16];       // per (b,pp,cg) partial sumsq
__device__ float d_cos[B_*P_];
__device__ int   d_sel[B_*P_];

__device__ __forceinline__ float warpReduce(float v) {
  #pragma unroll
  for (int o = 16; o > 0; o >>= 1) v += __shfl_down_sync(0xffffffffu, v, o);
  return v;
}

// ---------------------------------------------------- zero gsum (512 floats)
__global__ void k_zero() {
  int i = threadIdx.x;
  if (i < B_*C_) d_gsum[i] = 0.f;
}

// ------------------------------------------- per-patch stats (covered region)
// Block = (b, pp, channel-group of 16). Thread t owns weight bin widx == t:
// for channel c it reads q = ((t - 144*c) & 255) + 256*j (coalesced), since
// widx = (144*c + q) mod 256 == t. Fixed 11-trip predicated loop -> full
// unroll, 11 LDGs in flight. S/Q written as per-block partials (no atomics).
#define CG 16
__global__ __launch_bounds__(256) void k_stats(const float* __restrict__ x) {
  int bid = blockIdx.x;
  int cg = bid & 15;                 // C_/CG == 16 groups
  int pp = (bid >> 4) % P_;
  int b  = bid / (16 * P_);
  int ph = pp / NW, pw = pp - ph * NW;
  int t = threadIdx.x;
  int lane = t & 31, warp = t >> 5;

  const float* pbase = x + (size_t)b * C_ * PLANE + (size_t)(ph * PS) * W_ + pw * PS;

  float acc = 0.f;    // S bin t
  float qacc = 0.f;   // sum of squares
  #pragma unroll 1
  for (int cc = 0; cc < CG; ++cc) {
    int c = cg * CG + cc;
    const float* cb = pbase + (size_t)c * PLANE;
    int q0 = (t - 144 * c) & 255;
    float csum = 0.f;
    #pragma unroll
    for (int j = 0; j < 11; ++j) {
      int q = q0 + 256 * j;
      int kh = q / PS;
      int kw = q - kh * PS;
      float v = (q < QQ) ? __ldg(cb + kh * W_ + kw) : 0.f;
      acc += v;
      csum += v;
      qacc = fmaf(v, v, qacc);
    }
    csum = warpReduce(csum);
    if (lane == 0) atomicAdd(&d_gsum[b * C_ + c], csum);
  }
  d_S16[((size_t)(b * P_ + pp) * 16 + cg) * 256 + t] = acc;

  __shared__ float qred[8];
  qacc = warpReduce(qacc);
  if (lane == 0) qred[warp] = qacc;
  __syncthreads();
  if (warp == 0) {
    float v = (lane < 8) ? qred[lane] : 0.f;
    v = warpReduce(v);
    if (lane == 0) d_Q16[(b * P_ + pp) * 16 + cg] = v;
  }
}

// -------------------------------------------------- GAP over uncovered border
// border per plane: rows 0..467 cols 468..511 (468*44=20592) + rows 468..511
// all cols (44*512=22528) = 43120 elements.
__global__ __launch_bounds__(256) void k_border_g(const float* __restrict__ x) {
  int plane = blockIdx.y;                    // 0..B_*C_-1
  const float* pb = x + (size_t)plane * PLANE;
  float s = 0.f;
  for (int j = blockIdx.x * blockDim.x + threadIdx.x; j < 43120;
       j += gridDim.x * blockDim.x) {
    int r, col;
    if (j < 20592) { r = j / 44; col = 468 + (j - r * 44); }
    else           { int j2 = j - 20592; r = 468 + (j2 >> 9); col = j2 & 511; }
    s += pb[(size_t)r * W_ + col];
  }
  __shared__ float red[8];
  int lane = threadIdx.x & 31, warp = threadIdx.x >> 5;
  s = warpReduce(s);
  if (lane == 0) red[warp] = s;
  __syncthreads();
  if (warp == 0) {
    float v = (lane < 8) ? red[lane] : 0.f;
    v = warpReduce(v);
    if (lane == 0) atomicAdd(&d_gsum[plane], v);
  }
}

// --------------------------------------------- cosine per patch (grid 2*81)
__global__ __launch_bounds__(256) void k_cos() {
  int bp = blockIdx.x;               // b*81 + pp
  int b = bp / P_;
  int t = threadIdx.x;
  int lane = t & 31, warp = t >> 5;

  float g = d_gsum[b * C_ + t] * (1.0f / (float)PLANE);
  float s = 0.f;
  const float* Sp = d_S16 + (size_t)bp * 16 * 256 + t;
  #pragma unroll
  for (int cg = 0; cg < 16; ++cg) s += Sp[cg * 256];

  float dotv = s * g;
  float gg = g * g;
  __shared__ float rd[8], rg[8];
  dotv = warpReduce(dotv);
  gg = warpReduce(gg);
  if (lane == 0) { rd[warp] = dotv; rg[warp] = gg; }
  __syncthreads();
  if (t == 0) {
    float D = 0.f, G = 0.f;
    #pragma unroll
    for (int i = 0; i < 8; ++i) { D += rd[i]; G += rg[i]; }
    float q = 0.f;
    const float* Qp = d_Q16 + bp * 16;
    #pragma unroll
    for (int i = 0; i < 16; ++i) q += Qp[i];
    float gnorm = sqrtf(G) * (float)PS;
    float pnorm = sqrtf(q);
    d_cos[bp] = D / fmaxf(gnorm * pnorm, 1e-8f);
  }
}

// --------------------------------------------------- argmax/argmin -> sel[]
__global__ __launch_bounds__(128) void k_sel() {
  int b = blockIdx.x;
  int t = threadIdx.x;
  __shared__ float cs[P_];
  __shared__ int mm[2];
  if (t < P_) cs[t] = d_cos[b * P_ + t];
  __syncthreads();
  if (t == 0) {
    float vmax = cs[0], vmin = cs[0];
    int imax = 0, imin = 0;
    for (int i = 1; i < P_; ++i) {   // strict compare -> first occurrence (jnp)
      float cv = cs[i];
      if (cv > vmax) { vmax = cv; imax = i; }
      if (cv < vmin) { vmin = cv; imin = i; }
    }
    mm[0] = imax; mm[1] = imin;
  }
  __syncthreads();
  if (t < P_) d_sel[b * P_ + t] = (t == mm[0]) ? mm[1] : t;
}

// ------------------------------------------------------- apply mask (covered)
// Block = (b, pp, kh). Covers all 52 output columns of row h = ph*52+kh for
// all 256 channels. m = (kh*52 + kw)*256 + c; consecutive m => consecutive
// SOURCE addresses (float4 never straddles a source row or channel: 52 and
// 2704 are multiples of 4). Stage in dynamic smem [kw][c] stride 265 (STS
// conflict-free, LDS ~2-way), then float4 coalesced RMW of 208B channel-row
// segments.
__global__ __launch_bounds__(512) void k_apply(const float* __restrict__ x,
                                               float* __restrict__ out) {
  extern __shared__ float sbuf[];    // 52*265 floats = 55.1 KB
  int lin = blockIdx.x;
  int kh = lin % PS;
  int pp = (lin / PS) % P_;
  int b  = lin / (PS * P_);
  int ph = pp / NW, pw = pp - ph * NW;
  int sp = d_sel[b * P_ + pp];
  int sph = sp / NW, spw = sp - sph * NW;
  int t = threadIdx.x;

  const float* xb = x + (size_t)b * C_ * PLANE;
  const float* src = xb + (size_t)(sph * PS) * W_ + spw * PS;
  int mbase = kh * PS * 256;

  // gather 13312 source elements (3328 float4), source-linear (coalesced)
  for (int i4 = t; i4 < 3328; i4 += 512) {
    int i = i4 << 2;
    int kw = i >> 8;                 // element (kw, c), c in [0,256)
    int cl = i & 255;
    int m = mbase + i;
    int cs  = m / QQ;
    int r   = m - cs * QQ;
    int khs = r / PS;
    int kws = r - khs * PS;
    float4 v = *reinterpret_cast<const float4*>(src + (size_t)cs * PLANE +
                                                khs * W_ + kws);
    int si = kw * SB_STRIDE + cl;
    sbuf[si]     = v.x;
    sbuf[si + 1] = v.y;
    sbuf[si + 2] = v.z;
    sbuf[si + 3] = v.w;
  }
  __syncthreads();

  int h  = ph * PS + kh;
  int wb = pw * PS;
  // write side: per channel 13 float4 quads covering 52 cols (coalesced)
  for (int i4 = t; i4 < 3328; i4 += 512) {
    int col_ = i4 / 13;              // channel 0..255
    int kwq  = i4 - col_ * 13;
    int kw0  = kwq << 2;
    float m0v = sbuf[(kw0    ) * SB_STRIDE + col_];
    float m1v = sbuf[(kw0 + 1) * SB_STRIDE + col_];
    float m2v = sbuf[(kw0 + 2) * SB_STRIDE + col_];
    float m3v = sbuf[(kw0 + 3) * SB_STRIDE + col_];
    size_t off = ((size_t)(b * C_ + col_) * H_ + h) * W_ + wb + kw0;
    float4 xv = *reinterpret_cast<const float4*>(x + off);
    float4 ov;
    ov.x = m0v * xv.x;
    ov.y = m1v * xv.y;
    ov.z = m2v * xv.z;
    ov.w = m3v * xv.w;
    *reinterpret_cast<float4*>(out + off) = ov;
  }
}

// ------------------------------------------------------------ zero the border
// R1: 468 rows x 44 cols (11 quads), R2: 44 rows x 512 cols (128 quads)
__global__ __launch_bounds__(256) void k_border_out(float* __restrict__ out) {
  int plane = blockIdx.y;
  size_t pb = (size_t)plane * PLANE;
  float4 z = make_float4(0.f, 0.f, 0.f, 0.f);
  for (int i = blockIdx.x * blockDim.x + threadIdx.x; i < 10780;
       i += gridDim.x * blockDim.x) {
    size_t off;
    if (i < 5148) { int r = i / 11; int cq = i - r * 11;
                    off = pb + (size_t)r * W_ + 468 + (cq << 2); }
    else          { int j = i - 5148; int r = j >> 7; int cq = j & 127;
                    off = pb + (size_t)(468 + r) * W_ + (cq << 2); }
    *reinterpret_cast<float4*>(out + off) = z;
  }
}

extern "C" void kernel_launch(void* const* d_in, const int* in_sizes, int n_in,
                              void* d_out, int out_size) {
  (void)in_sizes; (void)n_in; (void)out_size;
  const float* x = (const float*)d_in[0];
  float* out = (float*)d_out;

  cudaFuncSetAttribute(k_apply, cudaFuncAttributeMaxDynamicSharedMemorySize,
                       PS * SB_STRIDE * sizeof(float));

  k_border_out<<<dim3(11, B_ * C_), 256>>>(out);
  k_zero<<<1, 512>>>();
  k_border_g<<<dim3(22, B_ * C_), 256>>>(x);
  k_stats<<<B_ * P_ * 16, 256>>>(x);            // <- ncu capture slot (4th)
  k_cos<<<B_ * P_, 256>>>();
  k_sel<<<B_, 128>>>();
  k_apply<<<B_ * P_ * PS, 512, PS * SB_STRIDE * sizeof(float)>>>(x, out);
}

// round 9
// speedup vs baseline: 1.3377x; 1.3377x over previous
#include <cuda_runtime.h>
#include <cstdint>
#include <cstddef>

#define B_    2
#define C_    256
#define H_    512
#define W_    512
#define PS    52
#define NH    9
#define NW    9
#define P_    81
#define QQ    2704         // PS*PS
#define PLANE (H_*W_)      // 262144

// Scratch (device globals: no allocations allowed)
__device__ float d_gsum[B_*C_];
__device__ float d_S16[B_*P_*16*256];   // per (b,pp,cg) partial weighted sums
__device__ float d_Q16[B_*P_*16];       // per (b,pp,cg) partial sumsq
__device__ float d_cos[B_*P_];
__device__ int   d_sel[B_*P_];

__device__ __forceinline__ float warpReduce(float v) {
  #pragma unroll
  for (int o = 16; o > 0; o >>= 1) v += __shfl_down_sync(0xffffffffu, v, o);
  return v;
}

// ---------------------------------------------------- zero gsum (512 floats)
__global__ void k_zero() {
  int i = threadIdx.x;
  if (i < B_*C_) d_gsum[i] = 0.f;
}

// ------------------------------------------- per-patch stats (covered region)
// Block = (b, pp, channel-group of 16). 4 lane-groups of 64; lane u of group g
// owns bins 4u..4u+3: for channel c it reads float4 at q = ((4u-144c)&255)
// + 256*j (widx of element q+k is 4u+k since 144c+q0 == 4u mod 256; kw == 0
// mod 4 so the float4 never crosses a source row). Group g handles channels
// cg*16 + g*4 + cc. Bins accumulate in registers -> smem merge; gsum via 2
// red-adds per channel.
#define CG 16
__global__ __launch_bounds__(256) void k_stats(const float* __restrict__ x) {
  __shared__ float4 sb4[4 * 64];     // [group][u] -> bins g? no: bins 4u..4u+3
  __shared__ float qred[8];
  int bid = blockIdx.x;
  int cg = bid & 15;                 // C_/CG == 16 groups
  int pp = (bid >> 4) % P_;
  int b  = bid / (16 * P_);
  int ph = pp / NW, pw = pp - ph * NW;
  int t = threadIdx.x;
  int lane = t & 31, warp = t >> 5;
  int g = t >> 6;                    // lane-group 0..3
  int u = t & 63;                    // 0..63, owns bins 4u..4u+3

  const float* pbase = x + (size_t)b * C_ * PLANE + (size_t)(ph * PS) * W_ + pw * PS;

  float a0 = 0.f, a1 = 0.f, a2 = 0.f, a3 = 0.f;  // bins 4u..4u+3
  float qacc = 0.f;                               // sum of squares
  #pragma unroll 1
  for (int cc = 0; cc < 4; ++cc) {
    int c = cg * CG + g * 4 + cc;
    const float* cb = pbase + (size_t)c * PLANE;
    int q0 = (4 * u - 144 * c) & 255;
    float csum = 0.f;
    #pragma unroll
    for (int j = 0; j < 11; ++j) {
      int q = q0 + 256 * j;
      if (q < QQ) {
        int kh = q / PS;
        int kw = q - kh * PS;
        float4 v = *reinterpret_cast<const float4*>(cb + kh * W_ + kw);
        a0 += v.x; a1 += v.y; a2 += v.z; a3 += v.w;
        csum += (v.x + v.y) + (v.z + v.w);
        qacc = fmaf(v.x, v.x, qacc);
        qacc = fmaf(v.y, v.y, qacc);
        qacc = fmaf(v.z, v.z, qacc);
        qacc = fmaf(v.w, v.w, qacc);
      }
    }
    csum = warpReduce(csum);
    if (lane == 0) atomicAdd(&d_gsum[b * C_ + c], csum);
  }
  sb4[g * 64 + u] = make_float4(a0, a1, a2, a3);

  qacc = warpReduce(qacc);
  if (lane == 0) qred[warp] = qacc;
  __syncthreads();

  // merge the 4 group-copies of bin t and store
  const float* sb = reinterpret_cast<const float*>(sb4);
  float S = sb[t] + sb[256 + t] + sb[512 + t] + sb[768 + t];
  d_S16[((size_t)(b * P_ + pp) * 16 + cg) * 256 + t] = S;

  if (warp == 0) {
    float v = (lane < 8) ? qred[lane] : 0.f;
    v = warpReduce(v);
    if (lane == 0) d_Q16[(b * P_ + pp) * 16 + cg] = v;
  }
}

// -------------------------------------------------- GAP over uncovered border
// border per plane: rows 0..467 cols 468..511 (468*44=20592) + rows 468..511
// all cols (44*512=22528) = 43120 elements.
__global__ __launch_bounds__(256) void k_border_g(const float* __restrict__ x) {
  int plane = blockIdx.y;                    // 0..B_*C_-1
  const float* pb = x + (size_t)plane * PLANE;
  float s = 0.f;
  for (int j = blockIdx.x * blockDim.x + threadIdx.x; j < 43120;
       j += gridDim.x * blockDim.x) {
    int r, col;
    if (j < 20592) { r = j / 44; col = 468 + (j - r * 44); }
    else           { int j2 = j - 20592; r = 468 + (j2 >> 9); col = j2 & 511; }
    s += pb[(size_t)r * W_ + col];
  }
  __shared__ float red[8];
  int lane = threadIdx.x & 31, warp = threadIdx.x >> 5;
  s = warpReduce(s);
  if (lane == 0) red[warp] = s;
  __syncthreads();
  if (warp == 0) {
    float v = (lane < 8) ? red[lane] : 0.f;
    v = warpReduce(v);
    if (lane == 0) atomicAdd(&d_gsum[plane], v);
  }
}

// --------------------------------------------- cosine per patch (grid 2*81)
__global__ __launch_bounds__(256) void k_cos() {
  int bp = blockIdx.x;               // b*81 + pp
  int b = bp / P_;
  int t = threadIdx.x;
  int lane = t & 31, warp = t >> 5;

  float g = d_gsum[b * C_ + t] * (1.0f / (float)PLANE);
  float s = 0.f;
  const float* Sp = d_S16 + (size_t)bp * 16 * 256 + t;
  #pragma unroll
  for (int cg = 0; cg < 16; ++cg) s += Sp[cg * 256];

  float dotv = s * g;
  float gg = g * g;
  __shared__ float rd[8], rg[8];
  dotv = warpReduce(dotv);
  gg = warpReduce(gg);
  if (lane == 0) { rd[warp] = dotv; rg[warp] = gg; }
  __syncthreads();
  if (t == 0) {
    float D = 0.f, G = 0.f;
    #pragma unroll
    for (int i = 0; i < 8; ++i) { D += rd[i]; G += rg[i]; }
    float q = 0.f;
    const float* Qp = d_Q16 + bp * 16;
    #pragma unroll
    for (int i = 0; i < 16; ++i) q += Qp[i];
    float gnorm = sqrtf(G) * (float)PS;
    float pnorm = sqrtf(q);
    d_cos[bp] = D / fmaxf(gnorm * pnorm, 1e-8f);
  }
}

// --------------------------------------------------- argmax/argmin -> sel[]
__global__ __launch_bounds__(128) void k_sel() {
  int b = blockIdx.x;
  int t = threadIdx.x;
  __shared__ float cs[P_];
  __shared__ int mm[2];
  if (t < P_) cs[t] = d_cos[b * P_ + t];
  __syncthreads();
  if (t == 0) {
    float vmax = cs[0], vmin = cs[0];
    int imax = 0, imin = 0;
    for (int i = 1; i < P_; ++i) {   // strict compare -> first occurrence (jnp)
      float cv = cs[i];
      if (cv > vmax) { vmax = cv; imax = i; }
      if (cv < vmin) { vmin = cv; imin = i; }
    }
    mm[0] = imax; mm[1] = imin;
  }
  __syncthreads();
  if (t < P_) d_sel[b * P_ + t] = (t == mm[0]) ? mm[1] : t;
}

// ------------------------------------------------------- apply mask (covered)
// Block = (b, pp, kh, channel-half of 128). Covers all 52 output columns of
// row h = ph*52+kh for 128 channels. m = (kh*52 + kw)*256 + c_out; consecutive
// m => consecutive SOURCE addresses (float4 never straddles a source row or
// channel: 52 and 2704 are multiples of 4). Stage in smem [kw][cl] with odd
// stride 137 (STS conflict-free, LDS <=2-way), then float4 coalesced
// read-modify-write of 208B channel-row segments.
__global__ __launch_bounds__(512) void k_apply(const float* __restrict__ x,
                                               float* __restrict__ out) {
  __shared__ float sbuf[PS * 137];   // 28.5 KB
  int lin = blockIdx.x;
  int chalf = lin & 1;
  int kh = (lin >> 1) % PS;
  int pp = ((lin >> 1) / PS) % P_;
  int b  = lin / (2 * PS * P_);
  int ph = pp / NW, pw = pp - ph * NW;
  int sp = d_sel[b * P_ + pp];
  int sph = sp / NW, spw = sp - sph * NW;
  int t = threadIdx.x;
  int c0 = chalf * 128;

  const float* xb = x + (size_t)b * C_ * PLANE;
  const float* src = xb + (size_t)(sph * PS) * W_ + spw * PS;
  int mbase = kh * PS * 256 + c0;

  // gather 6656 source elements (1664 float4), source-linear (coalesced)
  for (int i4 = t; i4 < 1664; i4 += 512) {
    int i = i4 << 2;
    int kw = i >> 7;                 // element (kw, cl), cl in [0,128)
    int cl = i & 127;
    int m = mbase + kw * 256 + cl;
    int cs  = m / QQ;
    int r   = m - cs * QQ;
    int khs = r / PS;
    int kws = r - khs * PS;
    float4 v = *reinterpret_cast<const float4*>(src + (size_t)cs * PLANE +
                                                khs * W_ + kws);
    int si = kw * 137 + cl;
    sbuf[si]     = v.x;
    sbuf[si + 1] = v.y;
    sbuf[si + 2] = v.z;
    sbuf[si + 3] = v.w;
  }
  __syncthreads();

  int h  = ph * PS + kh;
  int wb = pw * PS;
  // write side: per channel 13 float4 quads covering 52 cols (coalesced)
  for (int i4 = t; i4 < 1664; i4 += 512) {
    int col_ = i4 / 13;              // channel-local
    int kwq  = i4 - col_ * 13;
    int kw0  = kwq << 2;
    float m0v = sbuf[(kw0    ) * 137 + col_];
    float m1v = sbuf[(kw0 + 1) * 137 + col_];
    float m2v = sbuf[(kw0 + 2) * 137 + col_];
    float m3v = sbuf[(kw0 + 3) * 137 + col_];
    size_t off = ((size_t)(b * C_ + c0 + col_) * H_ + h) * W_ + wb + kw0;
    float4 xv = *reinterpret_cast<const float4*>(x + off);
    float4 ov;
    ov.x = m0v * xv.x;
    ov.y = m1v * xv.y;
    ov.z = m2v * xv.z;
    ov.w = m3v * xv.w;
    *reinterpret_cast<float4*>(out + off) = ov;
  }
}

// ------------------------------------------------------------ zero the border
// R1: 468 rows x 44 cols (11 quads), R2: 44 rows x 512 cols (128 quads)
__global__ __launch_bounds__(256) void k_border_out(float* __restrict__ out) {
  int plane = blockIdx.y;
  size_t pb = (size_t)plane * PLANE;
  float4 z = make_float4(0.f, 0.f, 0.f, 0.f);
  for (int i = blockIdx.x * blockDim.x + threadIdx.x; i < 10780;
       i += gridDim.x * blockDim.x) {
    size_t off;
    if (i < 5148) { int r = i / 11; int cq = i - r * 11;
                    off = pb + (size_t)r * W_ + 468 + (cq << 2); }
    else          { int j = i - 5148; int r = j >> 7; int cq = j & 127;
                    off = pb + (size_t)(468 + r) * W_ + (cq << 2); }
    *reinterpret_cast<float4*>(out + off) = z;
  }
}

extern "C" void kernel_launch(void* const* d_in, const int* in_sizes, int n_in,
                              void* d_out, int out_size) {
  (void)in_sizes; (void)n_in; (void)out_size;
  const float* x = (const float*)d_in[0];
  float* out = (float*)d_out;

  k_border_out<<<dim3(11, B_ * C_), 256>>>(out);
  k_zero<<<1, 512>>>();
  k_border_g<<<dim3(22, B_ * C_), 256>>>(x);
  k_stats<<<B_ * P_ * 16, 256>>>(x);            // <- ncu capture slot (4th)
  k_cos<<<B_ * P_, 256>>>();
  k_sel<<<B_, 128>>>();
  k_apply<<<B_ * P_ * PS * 2, 512>>>(x, out);
}

// round 10
// speedup vs baseline: 1.3857x; 1.0358x over previous
#include <cuda_runtime.h>
#include <cstdint>
#include <cstddef>
#include <math_constants.h>

#define B_    2
#define C_    256
#define H_    512
#define W_    512
#define PS    52
#define NH    9
#define NW    9
#define P_    81
#define QQ    2704         // PS*PS
#define PLANE (H_*W_)      // 262144

// Scratch (device globals: no allocations allowed)
__device__ float d_gp[B_*P_*256];       // per (b,pp) per-channel sums (covered)
__device__ float d_gb2[B_*C_*2];        // per-plane border sums (2 partials)
__device__ float d_S16[B_*P_*16*256];   // per (b,pp,cg) partial weighted sums
__device__ float d_Q16[B_*P_*16];       // per (b,pp,cg) partial sumsq
__device__ float d_cos[B_*P_];

__device__ __forceinline__ float warpReduce(float v) {
  #pragma unroll
  for (int o = 16; o > 0; o >>= 1) v += __shfl_down_sync(0xffffffffu, v, o);
  return v;
}

// ------------------------------------------- per-patch stats (covered region)
// Block = (b, pp, channel-group of 16). 4 lane-groups of 64; lane u of group g
// owns bins 4u..4u+3: for channel c it reads float4 at q = ((4u-144c)&255)
// + 256*j (widx of element q+k is 4u+k; kw == 0 mod 4 so the float4 never
// crosses a source row). Group g handles channels cg*16 + g*4 + cc. Bins
// accumulate in registers -> smem merge. Per-channel sums written as partials
// (no atomics anywhere).
#define CG 16
__global__ __launch_bounds__(256) void k_stats(const float* __restrict__ x) {
  __shared__ float4 sb4[4 * 64];     // [group][u] bins 4u..4u+3
  __shared__ float qred[8];
  __shared__ float sm_g[8 * 4];      // [warp][cc] per-warp channel partials
  int bid = blockIdx.x;
  int cg = bid & 15;                 // C_/CG == 16 groups
  int pp = (bid >> 4) % P_;
  int b  = bid / (16 * P_);
  int ph = pp / NW, pw = pp - ph * NW;
  int t = threadIdx.x;
  int lane = t & 31, warp = t >> 5;
  int g = t >> 6;                    // lane-group 0..3
  int u = t & 63;                    // 0..63, owns bins 4u..4u+3

  const float* pbase = x + (size_t)b * C_ * PLANE + (size_t)(ph * PS) * W_ + pw * PS;

  float a0 = 0.f, a1 = 0.f, a2 = 0.f, a3 = 0.f;  // bins 4u..4u+3
  float qacc = 0.f;                               // sum of squares
  #pragma unroll 1
  for (int cc = 0; cc < 4; ++cc) {
    int c = cg * CG + g * 4 + cc;
    const float* cb = pbase + (size_t)c * PLANE;
    int q0 = (4 * u - 144 * c) & 255;
    float csum = 0.f;
    #pragma unroll
    for (int j = 0; j < 11; ++j) {
      int q = q0 + 256 * j;
      if (q < QQ) {
        int kh = q / PS;
        int kw = q - kh * PS;
        float4 v = *reinterpret_cast<const float4*>(cb + kh * W_ + kw);
        a0 += v.x; a1 += v.y; a2 += v.z; a3 += v.w;
        csum += (v.x + v.y) + (v.z + v.w);
        qacc = fmaf(v.x, v.x, qacc);
        qacc = fmaf(v.y, v.y, qacc);
        qacc = fmaf(v.z, v.z, qacc);
        qacc = fmaf(v.w, v.w, qacc);
      }
    }
    csum = warpReduce(csum);
    if (lane == 0) sm_g[warp * 4 + cc] = csum;   // two warps per group
  }
  sb4[g * 64 + u] = make_float4(a0, a1, a2, a3);

  qacc = warpReduce(qacc);
  if (lane == 0) qred[warp] = qacc;
  __syncthreads();

  // merge the 4 group-copies of bin t and store
  const float* sb = reinterpret_cast<const float*>(sb4);
  float S = sb[t] + sb[256 + t] + sb[512 + t] + sb[768 + t];
  d_S16[((size_t)(b * P_ + pp) * 16 + cg) * 256 + t] = S;

  if (t < 16) {                      // channel c = cg*16 + t, t = g*4+cc
    int gg = t >> 2, cc = t & 3;
    float cs2 = sm_g[(2 * gg) * 4 + cc] + sm_g[(2 * gg + 1) * 4 + cc];
    // partial per (b,pp): unique writer, no atomics
    atomicAdd(&d_gp[(b * P_ + pp) * 256 + cg * 16 + t], 0.f);  // placeholder no-op removed below
    d_gp[(b * P_ + pp) * 256 + cg * 16 + t] = cs2;
  }
  if (warp == 0) {
    float v = (lane < 8) ? qred[lane] : 0.f;
    v = warpReduce(v);
    if (lane == 0) d_Q16[(b * P_ + pp) * 16 + cg] = v;
  }
}

// -------------------------------------------------- GAP over uncovered border
// border per plane: rows 0..467 cols 468..511 (468*44=20592) + rows 468..511
// all cols (44*512=22528) = 43120 elements. 2 partial blocks per plane.
__global__ __launch_bounds__(256) void k_border_g(const float* __restrict__ x) {
  int plane = blockIdx.y;                    // 0..B_*C_-1
  int half = blockIdx.x;                     // 0..1
  const float* pb = x + (size_t)plane * PLANE;
  float s = 0.f;
  #pragma unroll 4
  for (int j = half * 256 + threadIdx.x; j < 43120; j += 512) {
    int r, col;
    if (j < 20592) { r = j / 44; col = 468 + (j - r * 44); }
    else           { int j2 = j - 20592; r = 468 + (j2 >> 9); col = j2 & 511; }
    s += pb[(size_t)r * W_ + col];
  }
  __shared__ float red[8];
  int lane = threadIdx.x & 31, warp = threadIdx.x >> 5;
  s = warpReduce(s);
  if (lane == 0) red[warp] = s;
  __syncthreads();
  if (warp == 0) {
    float v = (lane < 8) ? red[lane] : 0.f;
    v = warpReduce(v);
    if (lane == 0) d_gb2[plane * 2 + half] = v;
  }
}

// --------------------------------------------- cosine per patch (grid 2*81)
// Also folds the gsum reduction (81 covered partials + 2 border partials).
__global__ __launch_bounds__(256) void k_cos() {
  int bp = blockIdx.x;               // b*81 + pp
  int b = bp / P_;
  int t = threadIdx.x;
  int lane = t & 31, warp = t >> 5;

  // g[t] = (sum over patches + border) / PLANE
  float gs = d_gb2[(b * C_ + t) * 2] + d_gb2[(b * C_ + t) * 2 + 1];
  const float* gp = d_gp + (size_t)b * P_ * 256 + t;
  #pragma unroll
  for (int i = 0; i < P_; ++i) gs += gp[i * 256];
  float g = gs * (1.0f / (float)PLANE);

  float s = 0.f;
  const float* Sp = d_S16 + (size_t)bp * 16 * 256 + t;
  #pragma unroll
  for (int cg = 0; cg < 16; ++cg) s += Sp[cg * 256];

  float dotv = s * g;
  float gg = g * g;
  __shared__ float rd[8], rg[8];
  dotv = warpReduce(dotv);
  gg = warpReduce(gg);
  if (lane == 0) { rd[warp] = dotv; rg[warp] = gg; }
  __syncthreads();
  if (t == 0) {
    float D = 0.f, G = 0.f;
    #pragma unroll
    for (int i = 0; i < 8; ++i) { D += rd[i]; G += rg[i]; }
    float q = 0.f;
    const float* Qp = d_Q16 + bp * 16;
    #pragma unroll
    for (int i = 0; i < 16; ++i) q += Qp[i];
    float gnorm = sqrtf(G) * (float)PS;
    float pnorm = sqrtf(q);
    d_cos[bp] = D / fmaxf(gnorm * pnorm, 1e-8f);
  }
}

// ------------------------------------------------------- apply mask (covered)
// Block = (b, pp, kh, channel-half of 128). Warp 0 first computes
// argmax/argmin of cos (tie -> lower index, jnp first-occurrence) to get the
// source patch. Then: gather source-linear float4 (m = (kh*52+kw)*256+c is
// consecutive source addresses; 52 and 2704 are multiples of 4 so no row or
// channel straddle), stage in smem [kw][cl] stride 137, float4 coalesced RMW
// of 208B channel-row segments.
__global__ __launch_bounds__(512) void k_apply(const float* __restrict__ x,
                                               float* __restrict__ out) {
  __shared__ float sbuf[PS * 137];   // 28.5 KB
  __shared__ int s_sp;
  int lin = blockIdx.x;
  int chalf = lin & 1;
  int kh = (lin >> 1) % PS;
  int pp = ((lin >> 1) / PS) % P_;
  int b  = lin / (2 * PS * P_);
  int ph = pp / NW, pw = pp - ph * NW;
  int t = threadIdx.x;
  int c0 = chalf * 128;

  if (t < 32) {                      // warp 0: argmax/argmin over 81 cos
    int lane = t;
    float vmax = -CUDART_INF_F, vmin = CUDART_INF_F;
    int imax = -1, imin = -1;
    #pragma unroll
    for (int k = 0; k < 3; ++k) {
      int i = lane + 32 * k;
      if (i < P_) {
        float cv = d_cos[b * P_ + i];
        if (cv > vmax || (cv == vmax && i < imax)) { vmax = cv; imax = i; }
        if (cv < vmin || (cv == vmin && i < imin)) { vmin = cv; imin = i; }
      }
    }
    #pragma unroll
    for (int o = 16; o > 0; o >>= 1) {
      float ov = __shfl_down_sync(0xffffffffu, vmax, o);
      int   oi = __shfl_down_sync(0xffffffffu, imax, o);
      if (ov > vmax || (ov == vmax && oi < imax)) { vmax = ov; imax = oi; }
      float nv = __shfl_down_sync(0xffffffffu, vmin, o);
      int   ni = __shfl_down_sync(0xffffffffu, imin, o);
      if (nv < vmin || (nv == vmin && ni < imin)) { vmin = nv; imin = ni; }
    }
    if (lane == 0) s_sp = (pp == imax) ? imin : pp;
  }
  __syncthreads();
  int sp = s_sp;
  int sph = sp / NW, spw = sp - sph * NW;

  const float* xb = x + (size_t)b * C_ * PLANE;
  const float* src = xb + (size_t)(sph * PS) * W_ + spw * PS;
  int mbase = kh * PS * 256 + c0;

  // gather 6656 source elements (1664 float4), source-linear (coalesced)
  for (int i4 = t; i4 < 1664; i4 += 512) {
    int i = i4 << 2;
    int kw = i >> 7;                 // element (kw, cl), cl in [0,128)
    int cl = i & 127;
    int m = mbase + kw * 256 + cl;
    int cs  = m / QQ;
    int r   = m - cs * QQ;
    int khs = r / PS;
    int kws = r - khs * PS;
    float4 v = *reinterpret_cast<const float4*>(src + (size_t)cs * PLANE +
                                                khs * W_ + kws);
    int si = kw * 137 + cl;
    sbuf[si]     = v.x;
    sbuf[si + 1] = v.y;
    sbuf[si + 2] = v.z;
    sbuf[si + 3] = v.w;
  }
  __syncthreads();

  int h  = ph * PS + kh;
  int wb = pw * PS;
  // write side: per channel 13 float4 quads covering 52 cols (coalesced)
  for (int i4 = t; i4 < 1664; i4 += 512) {
    int col_ = i4 / 13;              // channel-local
    int kwq  = i4 - col_ * 13;
    int kw0  = kwq << 2;
    float m0v = sbuf[(kw0    ) * 137 + col_];
    float m1v = sbuf[(kw0 + 1) * 137 + col_];
    float m2v = sbuf[(kw0 + 2) * 137 + col_];
    float m3v = sbuf[(kw0 + 3) * 137 + col_];
    size_t off = ((size_t)(b * C_ + c0 + col_) * H_ + h) * W_ + wb + kw0;
    float4 xv = *reinterpret_cast<const float4*>(x + off);
    float4 ov;
    ov.x = m0v * xv.x;
    ov.y = m1v * xv.y;
    ov.z = m2v * xv.z;
    ov.w = m3v * xv.w;
    *reinterpret_cast<float4*>(out + off) = ov;
  }
}

// ------------------------------------------------------------ zero the border
// R1: 468 rows x 44 cols (11 quads), R2: 44 rows x 512 cols (128 quads)
__global__ __launch_bounds__(256) void k_border_out(float* __restrict__ out) {
  int plane = blockIdx.y;
  size_t pb = (size_t)plane * PLANE;
  float4 z = make_float4(0.f, 0.f, 0.f, 0.f);
  for (int i = blockIdx.x * blockDim.x + threadIdx.x; i < 10780;
       i += gridDim.x * blockDim.x) {
    size_t off;
    if (i < 5148) { int r = i / 11; int cq = i - r * 11;
                    off = pb + (size_t)r * W_ + 468 + (cq << 2); }
    else          { int j = i - 5148; int r = j >> 7; int cq = j & 127;
                    off = pb + (size_t)(468 + r) * W_ + (cq << 2); }
    *reinterpret_cast<float4*>(out + off) = z;
  }
}

extern "C" void kernel_launch(void* const* d_in, const int* in_sizes, int n_in,
                              void* d_out, int out_size) {
  (void)in_sizes; (void)n_in; (void)out_size;
  const float* x = (const float*)d_in[0];
  float* out = (float*)d_out;

  k_stats<<<B_ * P_ * 16, 256>>>(x);
  k_border_g<<<dim3(2, B_ * C_), 256>>>(x);
  k_cos<<<B_ * P_, 256>>>();
  k_apply<<<B_ * P_ * PS * 2, 512>>>(x, out);   // <- ncu capture slot (4th)
  k_border_out<<<dim3(11, B_ * C_), 256>>>(out);
}

// round 12
// speedup vs baseline: 1.3923x; 1.0048x over previous
#include <cuda_runtime.h>
#include <cstdint>
#include <cstddef>
#include <math_constants.h>

#define B_    2
#define C_    256
#define H_    512
#define W_    512
#define PS    52
#define NH    9
#define NW    9
#define P_    81
#define QQ    2704         // PS*PS
#define PLANE (H_*W_)      // 262144

#define SBS   132          // staging stride (mult of 4; +XOR swizzle)

// Scratch (device globals: no allocations allowed)
__device__ float d_gp[B_*P_*256];       // per (b,pp) per-channel sums (covered)
__device__ float d_gb2[B_*C_*2];        // per-plane border sums (2 partials)
__device__ float d_S16[B_*P_*16*256];   // per (b,pp,cg) partial weighted sums
__device__ float d_Q16[B_*P_*16];       // per (b,pp,cg) partial sumsq
__device__ float d_cos[B_*P_];

__device__ __forceinline__ float warpReduce(float v) {
  #pragma unroll
  for (int o = 16; o > 0; o >>= 1) v += __shfl_down_sync(0xffffffffu, v, o);
  return v;
}

__device__ __forceinline__ int swz(int kw) {   // XOR swizzle, mult of 4
  return ((kw + (kw >> 2)) & 7) << 2;
}

// ------------------------------------------- per-patch stats (covered region)
// Block = (b, pp, channel-group of 16). 4 lane-groups of 64; lane u of group g
// owns bins 4u..4u+3: for channel c it reads float4 at q = ((4u-144c)&255)
// + 256*j (widx of element q+k is 4u+k; kw == 0 mod 4 so the float4 never
// crosses a source row). Group g handles channels cg*16 + g*4 + cc. Bins
// accumulate in registers -> smem merge. Per-channel sums written as partials
// (no atomics anywhere).
#define CG 16
__global__ __launch_bounds__(256) void k_stats(const float* __restrict__ x) {
  __shared__ float4 sb4[4 * 64];     // [group][u] bins 4u..4u+3
  __shared__ float qred[8];
  __shared__ float sm_g[8 * 4];      // [warp][cc] per-warp channel partials
  int bid = blockIdx.x;
  int cg = bid & 15;                 // C_/CG == 16 groups
  int pp = (bid >> 4) % P_;
  int b  = bid / (16 * P_);
  int ph = pp / NW, pw = pp - ph * NW;
  int t = threadIdx.x;
  int lane = t & 31, warp = t >> 5;
  int g = t >> 6;                    // lane-group 0..3
  int u = t & 63;                    // 0..63, owns bins 4u..4u+3

  const float* pbase = x + (size_t)b * C_ * PLANE + (size_t)(ph * PS) * W_ + pw * PS;

  float a0 = 0.f, a1 = 0.f, a2 = 0.f, a3 = 0.f;  // bins 4u..4u+3
  float qacc = 0.f;                               // sum of squares
  #pragma unroll 1
  for (int cc = 0; cc < 4; ++cc) {
    int c = cg * CG + g * 4 + cc;
    const float* cb = pbase + (size_t)c * PLANE;
    int q0 = (4 * u - 144 * c) & 255;
    float csum = 0.f;
    #pragma unroll
    for (int j = 0; j < 11; ++j) {
      int q = q0 + 256 * j;
      if (q < QQ) {
        int kh = q / PS;
        int kw = q - kh * PS;
        float4 v = *reinterpret_cast<const float4*>(cb + kh * W_ + kw);
        a0 += v.x; a1 += v.y; a2 += v.z; a3 += v.w;
        csum += (v.x + v.y) + (v.z + v.w);
        qacc = fmaf(v.x, v.x, qacc);
        qacc = fmaf(v.y, v.y, qacc);
        qacc = fmaf(v.z, v.z, qacc);
        qacc = fmaf(v.w, v.w, qacc);
      }
    }
    csum = warpReduce(csum);
    if (lane == 0) sm_g[warp * 4 + cc] = csum;   // two warps per group
  }
  sb4[g * 64 + u] = make_float4(a0, a1, a2, a3);

  qacc = warpReduce(qacc);
  if (lane == 0) qred[warp] = qacc;
  __syncthreads();

  // merge the 4 group-copies of bin t and store
  const float* sb = reinterpret_cast<const float*>(sb4);
  float S = sb[t] + sb[256 + t] + sb[512 + t] + sb[768 + t];
  d_S16[((size_t)(b * P_ + pp) * 16 + cg) * 256 + t] = S;

  if (t < 16) {                      // channel c = cg*16 + t, t = g*4+cc
    int gg = t >> 2, cc = t & 3;
    float cs2 = sm_g[(2 * gg) * 4 + cc] + sm_g[(2 * gg + 1) * 4 + cc];
    d_gp[(b * P_ + pp) * 256 + cg * 16 + t] = cs2;  // unique writer
  }
  if (warp == 0) {
    float v = (lane < 8) ? qred[lane] : 0.f;
    v = warpReduce(v);
    if (lane == 0) d_Q16[(b * P_ + pp) * 16 + cg] = v;
  }
}

// -------------------------------------------------- GAP over uncovered border
// border per plane: rows 0..467 cols 468..511 (468*44=20592) + rows 468..511
// all cols (44*512=22528) = 43120 elements. 2 partial blocks per plane.
__global__ __launch_bounds__(256) void k_border_g(const float* __restrict__ x) {
  int plane = blockIdx.y;                    // 0..B_*C_-1
  int half = blockIdx.x;                     // 0..1
  const float* pb = x + (size_t)plane * PLANE;
  float s = 0.f;
  #pragma unroll 4
  for (int j = half * 256 + threadIdx.x; j < 43120; j += 512) {
    int r, col;
    if (j < 20592) { r = j / 44; col = 468 + (j - r * 44); }
    else           { int j2 = j - 20592; r = 468 + (j2 >> 9); col = j2 & 511; }
    s += pb[(size_t)r * W_ + col];
  }
  __shared__ float red[8];
  int lane = threadIdx.x & 31, warp = threadIdx.x >> 5;
  s = warpReduce(s);
  if (lane == 0) red[warp] = s;
  __syncthreads();
  if (warp == 0) {
    float v = (lane < 8) ? red[lane] : 0.f;
    v = warpReduce(v);
    if (lane == 0) d_gb2[plane * 2 + half] = v;
  }
}

// --------------------------------------------- cosine per patch (grid 2*81)
// Also folds the gsum reduction (81 covered partials + 2 border partials).
__global__ __launch_bounds__(256) void k_cos() {
  int bp = blockIdx.x;               // b*81 + pp
  int b = bp / P_;
  int t = threadIdx.x;
  int lane = t & 31, warp = t >> 5;

  // g[t] = (sum over patches + border) / PLANE
  float gs = d_gb2[(b * C_ + t) * 2] + d_gb2[(b * C_ + t) * 2 + 1];
  const float* gp = d_gp + (size_t)b * P_ * 256 + t;
  #pragma unroll
  for (int i = 0; i < P_; ++i) gs += gp[i * 256];
  float g = gs * (1.0f / (float)PLANE);

  float s = 0.f;
  const float* Sp = d_S16 + (size_t)bp * 16 * 256 + t;
  #pragma unroll
  for (int cg = 0; cg < 16; ++cg) s += Sp[cg * 256];

  float dotv = s * g;
  float gg = g * g;
  __shared__ float rd[8], rg[8];
  dotv = warpReduce(dotv);
  gg = warpReduce(gg);
  if (lane == 0) { rd[warp] = dotv; rg[warp] = gg; }
  __syncthreads();
  if (t == 0) {
    float D = 0.f, G = 0.f;
    #pragma unroll
    for (int i = 0; i < 8; ++i) { D += rd[i]; G += rg[i]; }
    float q = 0.f;
    const float* Qp = d_Q16 + bp * 16;
    #pragma unroll
    for (int i = 0; i < 16; ++i) q += Qp[i];
    float gnorm = sqrtf(G) * (float)PS;
    float pnorm = sqrtf(q);
    d_cos[bp] = D / fmaxf(gnorm * pnorm, 1e-8f);
  }
}

// ------------------------------------------------------- apply mask (covered)
// Block = (b, pp, kh, channel-half of 128). Warp 0 computes argmax/argmin of
// cos (tie -> lower index) to get the source patch. Gather is source-linear
// float4 (m = (kh*52+kw)*256+c is consecutive source addresses; 52 and 2704
// are multiples of 4 so no row/channel straddle). Staging smem layout:
// word(kw, cl) = kw*132 + (cl ^ swz(kw)). All lanes of a warp share kw ->
// STS.128, conflict-free (XOR permutes 16B groups). Read side scalar LDS,
// banks spread by the kwq-dependent swizzle (5 coprime 8) -> ~1.4-way.
__global__ __launch_bounds__(512) void k_apply(const float* __restrict__ x,
                                               float* __restrict__ out) {
  __shared__ float sbuf[PS * SBS];   // 27.5 KB
  __shared__ int s_sp;
  int lin = blockIdx.x;
  int chalf = lin & 1;
  int kh = (lin >> 1) % PS;
  int pp = ((lin >> 1) / PS) % P_;
  int b  = lin / (2 * PS * P_);
  int ph = pp / NW, pw = pp - ph * NW;
  int t = threadIdx.x;
  int c0 = chalf * 128;

  if (t < 32) {                      // warp 0: argmax/argmin over 81 cos
    int lane = t;
    float vmax = -CUDART_INF_F, vmin = CUDART_INF_F;
    int imax = -1, imin = -1;
    #pragma unroll
    for (int k = 0; k < 3; ++k) {
      int i = lane + 32 * k;
      if (i < P_) {
        float cv = d_cos[b * P_ + i];
        if (cv > vmax || (cv == vmax && i < imax)) { vmax = cv; imax = i; }
        if (cv < vmin || (cv == vmin && i < imin)) { vmin = cv; imin = i; }
      }
    }
    #pragma unroll
    for (int o = 16; o > 0; o >>= 1) {
      float ov = __shfl_down_sync(0xffffffffu, vmax, o);
      int   oi = __shfl_down_sync(0xffffffffu, imax, o);
      if (ov > vmax || (ov == vmax && oi < imax)) { vmax = ov; imax = oi; }
      float nv = __shfl_down_sync(0xffffffffu, vmin, o);
      int   ni = __shfl_down_sync(0xffffffffu, imin, o);
      if (nv < vmin || (nv == vmin && ni < imin)) { vmin = nv; imin = ni; }
    }
    if (lane == 0) s_sp = (pp == imax) ? imin : pp;
  }
  __syncthreads();
  int sp = s_sp;
  int sph = sp / NW, spw = sp - sph * NW;

  const float* xb = x + (size_t)b * C_ * PLANE;
  const float* src = xb + (size_t)(sph * PS) * W_ + spw * PS;
  int mbase = kh * PS * 256 + c0;

  // gather 6656 source elements (1664 float4), source-linear (coalesced)
  for (int i4 = t; i4 < 1664; i4 += 512) {
    int i = i4 << 2;
    int kw = i >> 7;                 // element (kw, cl), cl in [0,128)
    int cl = i & 127;
    int m = mbase + kw * 256 + cl;
    int cs  = m / QQ;
    int r   = m - cs * QQ;
    int khs = r / PS;
    int kws = r - khs * PS;
    float4 v = *reinterpret_cast<const float4*>(src + (size_t)cs * PLANE +
                                                khs * W_ + kws);
    int si = kw * SBS + (cl ^ swz(kw));          // 16B-aligned
    *reinterpret_cast<float4*>(&sbuf[si]) = v;   // STS.128 conflict-free
  }
  __syncthreads();

  int h  = ph * PS + kh;
  int wb = pw * PS;
  // write side: per channel 13 float4 quads covering 52 cols (coalesced)
  for (int i4 = t; i4 < 1664; i4 += 512) {
    int col_ = i4 / 13;              // channel-local
    int kwq  = i4 - col_ * 13;
    int kw0  = kwq << 2;
    float m0v = sbuf[(kw0    ) * SBS + (col_ ^ swz(kw0    ))];
    float m1v = sbuf[(kw0 + 1) * SBS + (col_ ^ swz(kw0 + 1))];
    float m2v = sbuf[(kw0 + 2) * SBS + (col_ ^ swz(kw0 + 2))];
    float m3v = sbuf[(kw0 + 3) * SBS + (col_ ^ swz(kw0 + 3))];
    size_t off = ((size_t)(b * C_ + c0 + col_) * H_ + h) * W_ + wb + kw0;
    float4 xv = *reinterpret_cast<const float4*>(x + off);
    float4 ov;
    ov.x = m0v * xv.x;
    ov.y = m1v * xv.y;
    ov.z = m2v * xv.z;
    ov.w = m3v * xv.w;
    *reinterpret_cast<float4*>(out + off) = ov;
  }
}

// ------------------------------------------------------------ zero the border
// R1: 468 rows x 44 cols (11 quads), R2: 44 rows x 512 cols (128 quads)
__global__ __launch_bounds__(256) void k_border_out(float* __restrict__ out) {
  int plane = blockIdx.y;
  size_t pb = (size_t)plane * PLANE;
  float4 z = make_float4(0.f, 0.f, 0.f, 0.f);
  for (int i = blockIdx.x * blockDim.x + threadIdx.x; i < 10780;
       i += gridDim.x * blockDim.x) {
    size_t off;
    if (i < 5148) { int r = i / 11; int cq = i - r * 11;
                    off = pb + (size_t)r * W_ + 468 + (cq << 2); }
    else          { int j = i - 5148; int r = j >> 7; int cq = j & 127;
                    off = pb + (size_t)(468 + r) * W_ + (cq << 2); }
    *reinterpret_cast<float4*>(out + off) = z;
  }
}

extern "C" void kernel_launch(void* const* d_in, const int* in_sizes, int n_in,
                              void* d_out, int out_size) {
  (void)in_sizes; (void)n_in; (void)out_size;
  const float* x = (const float*)d_in[0];
  float* out = (float*)d_out;

  k_stats<<<B_ * P_ * 16, 256>>>(x);
  k_border_g<<<dim3(2, B_ * C_), 256>>>(x);
  k_cos<<<B_ * P_, 256>>>();
  k_apply<<<B_ * P_ * PS * 2, 512>>>(x, out);   // <- ncu capture slot (4th)
  k_border_out<<<dim3(11, B_ * C_), 256>>>(out);
}

// round 13
// speedup vs baseline: 1.4755x; 1.0598x over previous
#include <cuda_runtime.h>
#include <cstdint>
#include <cstddef>
#include <math_constants.h>

#define B_    2
#define C_    256
#define H_    512
#define W_    512
#define PS    52
#define NH    9
#define NW    9
#define P_    81
#define QQ    2704         // PS*PS
#define PLANE (H_*W_)      // 262144

#define SBS   132          // staging stride (mult of 4; +XOR swizzle)

// Scratch (device globals: no allocations allowed)
__device__ float d_gp[B_*P_*256];       // per (b,pp) per-channel sums (covered)
__device__ float d_gb2[B_*C_*2];        // per-plane border sums (2 partials)
__device__ float d_S16[B_*P_*16*256];   // per (b,pp,cg) partial weighted sums
__device__ float d_Q16[B_*P_*16];       // per (b,pp,cg) partial sumsq
__device__ float d_cos[B_*P_];

__device__ __forceinline__ float warpReduce(float v) {
  #pragma unroll
  for (int o = 16; o > 0; o >>= 1) v += __shfl_down_sync(0xffffffffu, v, o);
  return v;
}

__device__ __forceinline__ int swz(int kw) {   // XOR swizzle, mult of 4
  return ((kw + (kw >> 2)) & 7) << 2;
}

__device__ __forceinline__ void cp16(uint32_t saddr, const void* gaddr) {
  asm volatile("cp.async.cg.shared.global [%0], [%1], 16;\n"
               :: "r"(saddr), "l"(gaddr));
}

// ------------------------------------------- per-patch stats (covered region)
// Block = (b, pp, channel-group of 16). 4 lane-groups of 64; lane u of group g
// owns bins 4u..4u+3: for channel c it reads float4 at q = ((4u-144c)&255)
// + 256*j (widx of element q+k is 4u+k; kw == 0 mod 4 so the float4 never
// crosses a source row). Group g handles channels cg*16 + g*4 + cc. Bins
// accumulate in registers -> smem merge. No atomics anywhere.
#define CG 16
__global__ __launch_bounds__(256) void k_stats(const float* __restrict__ x) {
  __shared__ float4 sb4[4 * 64];     // [group][u] bins 4u..4u+3
  __shared__ float qred[8];
  __shared__ float sm_g[8 * 4];      // [warp][cc] per-warp channel partials
  int bid = blockIdx.x;
  int cg = bid & 15;                 // C_/CG == 16 groups
  int pp = (bid >> 4) % P_;
  int b  = bid / (16 * P_);
  int ph = pp / NW, pw = pp - ph * NW;
  int t = threadIdx.x;
  int lane = t & 31, warp = t >> 5;
  int g = t >> 6;                    // lane-group 0..3
  int u = t & 63;                    // 0..63, owns bins 4u..4u+3

  const float* pbase = x + (size_t)b * C_ * PLANE + (size_t)(ph * PS) * W_ + pw * PS;

  float a0 = 0.f, a1 = 0.f, a2 = 0.f, a3 = 0.f;  // bins 4u..4u+3
  float qacc = 0.f;                               // sum of squares
  #pragma unroll 1
  for (int cc = 0; cc < 4; ++cc) {
    int c = cg * CG + g * 4 + cc;
    const float* cb = pbase + (size_t)c * PLANE;
    int q0 = (4 * u - 144 * c) & 255;
    float csum = 0.f;
    #pragma unroll
    for (int j = 0; j < 11; ++j) {
      int q = q0 + 256 * j;
      if (q < QQ) {
        int kh = q / PS;
        int kw = q - kh * PS;
        float4 v = *reinterpret_cast<const float4*>(cb + kh * W_ + kw);
        a0 += v.x; a1 += v.y; a2 += v.z; a3 += v.w;
        csum += (v.x + v.y) + (v.z + v.w);
        qacc = fmaf(v.x, v.x, qacc);
        qacc = fmaf(v.y, v.y, qacc);
        qacc = fmaf(v.z, v.z, qacc);
        qacc = fmaf(v.w, v.w, qacc);
      }
    }
    csum = warpReduce(csum);
    if (lane == 0) sm_g[warp * 4 + cc] = csum;   // two warps per group
  }
  sb4[g * 64 + u] = make_float4(a0, a1, a2, a3);

  qacc = warpReduce(qacc);
  if (lane == 0) qred[warp] = qacc;
  __syncthreads();

  // merge the 4 group-copies of bin t and store
  const float* sb = reinterpret_cast<const float*>(sb4);
  float S = sb[t] + sb[256 + t] + sb[512 + t] + sb[768 + t];
  d_S16[((size_t)(b * P_ + pp) * 16 + cg) * 256 + t] = S;

  if (t < 16) {                      // channel c = cg*16 + t, t = g*4+cc
    int gg = t >> 2, cc = t & 3;
    float cs2 = sm_g[(2 * gg) * 4 + cc] + sm_g[(2 * gg + 1) * 4 + cc];
    d_gp[(b * P_ + pp) * 256 + cg * 16 + t] = cs2;  // unique writer
  }
  if (warp == 0) {
    float v = (lane < 8) ? qred[lane] : 0.f;
    v = warpReduce(v);
    if (lane == 0) d_Q16[(b * P_ + pp) * 16 + cg] = v;
  }
}

// -------------------------------------------------- GAP over uncovered border
__global__ __launch_bounds__(256) void k_border_g(const float* __restrict__ x) {
  int plane = blockIdx.y;                    // 0..B_*C_-1
  int half = blockIdx.x;                     // 0..1
  const float* pb = x + (size_t)plane * PLANE;
  float s = 0.f;
  #pragma unroll 4
  for (int j = half * 256 + threadIdx.x; j < 43120; j += 512) {
    int r, col;
    if (j < 20592) { r = j / 44; col = 468 + (j - r * 44); }
    else           { int j2 = j - 20592; r = 468 + (j2 >> 9); col = j2 & 511; }
    s += pb[(size_t)r * W_ + col];
  }
  __shared__ float red[8];
  int lane = threadIdx.x & 31, warp = threadIdx.x >> 5;
  s = warpReduce(s);
  if (lane == 0) red[warp] = s;
  __syncthreads();
  if (warp == 0) {
    float v = (lane < 8) ? red[lane] : 0.f;
    v = warpReduce(v);
    if (lane == 0) d_gb2[plane * 2 + half] = v;
  }
}

// --------------------------------------------- cosine per patch (grid 2*81)
__global__ __launch_bounds__(256) void k_cos() {
  int bp = blockIdx.x;               // b*81 + pp
  int b = bp / P_;
  int t = threadIdx.x;
  int lane = t & 31, warp = t >> 5;

  float gs = d_gb2[(b * C_ + t) * 2] + d_gb2[(b * C_ + t) * 2 + 1];
  const float* gp = d_gp + (size_t)b * P_ * 256 + t;
  #pragma unroll
  for (int i = 0; i < P_; ++i) gs += gp[i * 256];
  float g = gs * (1.0f / (float)PLANE);

  float s = 0.f;
  const float* Sp = d_S16 + (size_t)bp * 16 * 256 + t;
  #pragma unroll
  for (int cg = 0; cg < 16; ++cg) s += Sp[cg * 256];

  float dotv = s * g;
  float gg = g * g;
  __shared__ float rd[8], rg[8];
  dotv = warpReduce(dotv);
  gg = warpReduce(gg);
  if (lane == 0) { rd[warp] = dotv; rg[warp] = gg; }
  __syncthreads();
  if (t == 0) {
    float D = 0.f, G = 0.f;
    #pragma unroll
    for (int i = 0; i < 8; ++i) { D += rd[i]; G += rg[i]; }
    float q = 0.f;
    const float* Qp = d_Q16 + bp * 16;
    #pragma unroll
    for (int i = 0; i < 16; ++i) q += Qp[i];
    float gnorm = sqrtf(G) * (float)PS;
    float pnorm = sqrtf(q);
    d_cos[bp] = D / fmaxf(gnorm * pnorm, 1e-8f);
  }
}

// ------------------------------------------------------- apply mask (covered)
// Block = (b, pp, kh, channel-half of 128). Warp 0 computes argmax/argmin of
// cos to pick the source patch. Pipeline: (1a) gather via cp.async.cg into
// swizzled smem (no reg dependency), (1b) prefetch the aligned multiplicand
// float4s into registers, wait+barrier, (2) LDS+FFMA+STG only. All ~7 global
// loads per thread are in flight before the barrier.
__global__ __launch_bounds__(512, 3) void k_apply(const float* __restrict__ x,
                                                  float* __restrict__ out) {
  __shared__ float sbuf[PS * SBS];   // 27.5 KB
  __shared__ int s_sp;
  int lin = blockIdx.x;
  int chalf = lin & 1;
  int kh = (lin >> 1) % PS;
  int pp = ((lin >> 1) / PS) % P_;
  int b  = lin / (2 * PS * P_);
  int ph = pp / NW, pw = pp - ph * NW;
  int t = threadIdx.x;
  int c0 = chalf * 128;

  if (t < 32) {                      // warp 0: argmax/argmin over 81 cos
    int lane = t;
    float vmax = -CUDART_INF_F, vmin = CUDART_INF_F;
    int imax = -1, imin = -1;
    #pragma unroll
    for (int k = 0; k < 3; ++k) {
      int i = lane + 32 * k;
      if (i < P_) {
        float cv = d_cos[b * P_ + i];
        if (cv > vmax || (cv == vmax && i < imax)) { vmax = cv; imax = i; }
        if (cv < vmin || (cv == vmin && i < imin)) { vmin = cv; imin = i; }
      }
    }
    #pragma unroll
    for (int o = 16; o > 0; o >>= 1) {
      float ov = __shfl_down_sync(0xffffffffu, vmax, o);
      int   oi = __shfl_down_sync(0xffffffffu, imax, o);
      if (ov > vmax || (ov == vmax && oi < imax)) { vmax = ov; imax = oi; }
      float nv = __shfl_down_sync(0xffffffffu, vmin, o);
      int   ni = __shfl_down_sync(0xffffffffu, imin, o);
      if (nv < vmin || (nv == vmin && ni < imin)) { vmin = nv; imin = ni; }
    }
    if (lane == 0) s_sp = (pp == imax) ? imin : pp;
  }
  __syncthreads();
  int sp = s_sp;
  int sph = sp / NW, spw = sp - sph * NW;

  const float* xb = x + (size_t)b * C_ * PLANE;
  const float* src = xb + (size_t)(sph * PS) * W_ + spw * PS;
  int mbase = kh * PS * 256 + c0;
  int h  = ph * PS + kh;
  int wb = pw * PS;
  uint32_t sb_u32 = (uint32_t)__cvta_generic_to_shared(sbuf);

  // 1a: gather 1664 float4 via cp.async (source-linear, coalesced;
  //     m = mbase + i is consecutive source addresses, no row/chan straddle)
  #pragma unroll
  for (int k = 0; k < 4; ++k) {
    int i4 = t + 512 * k;
    if (i4 < 1664) {
      int i = i4 << 2;
      int kw = i >> 7;
      int cl = i & 127;
      int m = mbase + kw * 256 + cl;
      int cs  = m / QQ;
      int r   = m - cs * QQ;
      int khs = r / PS;
      int kws = r - khs * PS;
      int si = kw * SBS + (cl ^ swz(kw));
      cp16(sb_u32 + (si << 2), src + (size_t)cs * PLANE + khs * W_ + kws);
    }
  }
  asm volatile("cp.async.commit_group;\n" ::: "memory");

  // 1b: prefetch multiplicand float4s (independent of smem)
  float4 pre[4];
  #pragma unroll
  for (int k = 0; k < 4; ++k) {
    int i4 = t + 512 * k;
    if (i4 < 1664) {
      int col_ = i4 / 13;
      int kw0  = (i4 - col_ * 13) << 2;
      size_t off = ((size_t)(b * C_ + c0 + col_) * H_ + h) * W_ + wb + kw0;
      pre[k] = *reinterpret_cast<const float4*>(x + off);
    }
  }

  asm volatile("cp.async.wait_group 0;\n" ::: "memory");
  __syncthreads();

  // 2: smem reads + FFMA + coalesced float4 stores
  #pragma unroll
  for (int k = 0; k < 4; ++k) {
    int i4 = t + 512 * k;
    if (i4 < 1664) {
      int col_ = i4 / 13;
      int kwq  = i4 - col_ * 13;
      int kw0  = kwq << 2;
      float m0v = sbuf[(kw0    ) * SBS + (col_ ^ swz(kw0    ))];
      float m1v = sbuf[(kw0 + 1) * SBS + (col_ ^ swz(kw0 + 1))];
      float m2v = sbuf[(kw0 + 2) * SBS + (col_ ^ swz(kw0 + 2))];
      float m3v = sbuf[(kw0 + 3) * SBS + (col_ ^ swz(kw0 + 3))];
      size_t off = ((size_t)(b * C_ + c0 + col_) * H_ + h) * W_ + wb + kw0;
      float4 ov;
      ov.x = m0v * pre[k].x;
      ov.y = m1v * pre[k].y;
      ov.z = m2v * pre[k].z;
      ov.w = m3v * pre[k].w;
      *reinterpret_cast<float4*>(out + off) = ov;
    }
  }
}

// ------------------------------------------------------------ zero the border
__global__ __launch_bounds__(256) void k_border_out(float* __restrict__ out) {
  int plane = blockIdx.y;
  size_t pb = (size_t)plane * PLANE;
  float4 z = make_float4(0.f, 0.f, 0.f, 0.f);
  for (int i = blockIdx.x * blockDim.x + threadIdx.x; i < 10780;
       i += gridDim.x * blockDim.x) {
    size_t off;
    if (i < 5148) { int r = i / 11; int cq = i - r * 11;
                    off = pb + (size_t)r * W_ + 468 + (cq << 2); }
    else          { int j = i - 5148; int r = j >> 7; int cq = j & 127;
                    off = pb + (size_t)(468 + r) * W_ + (cq << 2); }
    *reinterpret_cast<float4*>(out + off) = z;
  }
}

extern "C" void kernel_launch(void* const* d_in, const int* in_sizes, int n_in,
                              void* d_out, int out_size) {
  (void)in_sizes; (void)n_in; (void)out_size;
  const float* x = (const float*)d_in[0];
  float* out = (float*)d_out;

  k_stats<<<B_ * P_ * 16, 256>>>(x);
  k_border_g<<<dim3(2, B_ * C_), 256>>>(x);
  k_cos<<<B_ * P_, 256>>>();
  k_apply<<<B_ * P_ * PS * 2, 512>>>(x, out);   // <- ncu capture slot (4th)
  k_border_out<<<dim3(11, B_ * C_), 256>>>(out);
}